// round 6
// baseline (speedup 1.0000x reference)
#include <cuda_runtime.h>
#include <cstdint>

// ---------------------------------------------------------------------------
// Constants (derived at compile time from reference _compute_offsets()):
//   Level l: scale = 16*2^l - 1, resolution = 16*2^l, verts/axis r1 = 16*2^l+1
//   Dense levels: 0 (r1=17, off 0, size 4920), 1 (r1=33, off 4920, size 35944),
//                 2 (r1=65, off 40864, size 274632)
//   Hashed levels 3..15: 2^19 entries each -> mask; off = 315496+(l-3)*524288
//   TOTAL = 7131240
// ---------------------------------------------------------------------------

#define TOTAL_PARAMS 7131240
#define DENSE_TOTAL  315496
#define HASH_MASK    0x7FFFFu
#define PRIME_Y      2654435761u
#define PRIME_Z      805459861u

// Accumulator: {sum.x, sum.y, count, pad} per vertex -> single vector RED.128
// per scattered point. Zero-initialized at module load; re-zeroed each call by
// zero_acc (overlapped with encode).
__device__ __align__(16) float4 g_acc[TOTAL_PARAMS];     // 114 MB
// Finalized table (float2 per vertex), written by finalize.
__device__ __align__(16) float2 g_table[TOTAL_PARAMS];   //  57 MB
// Dense-level pair table: g_dense4[i] = {table[i], table[i+1]} so the two
// x-neighbor corners load as one aligned float4 (halves dense gathers).
__device__ __align__(16) float4 g_dense4[DENSE_TOTAL];   //   5 MB

// ---------------------------------------------------------------------------
// Scatter: one 16B vector atomic per point (sm_90+ RED.128), accumulating
// both the embedding sum and the count in the same L2 line.
// ---------------------------------------------------------------------------
__global__ void __launch_bounds__(256) scatter_kernel(
    const float2* __restrict__ emb, const int* __restrict__ sidx, int n) {
    int i = blockIdx.x * blockDim.x + threadIdx.x;
    if (i >= n) return;
    int idx = sidx[i];
    float2 e = emb[i];
    atomicAdd(&g_acc[idx], make_float4(e.x, e.y, 1.0f, 0.0f));
}

// ---------------------------------------------------------------------------
// Finalize: table[i] = count>0 ? sums/count : fs[i]. Does NOT reset g_acc;
// the reset runs on a side stream concurrently with encode.
// ---------------------------------------------------------------------------
__global__ void __launch_bounds__(256) finalize_kernel(
    const float2* __restrict__ fs, int n) {
    int i = blockIdx.x * blockDim.x + threadIdx.x;
    if (i >= n) return;
    float4 a = g_acc[i];
    float2 v;
    if (a.z > 0.5f) {
        float inv = 1.0f / a.z;
        v.x = a.x * inv;
        v.y = a.y * inv;
    } else {
        v = fs[i];
    }
    g_table[i] = v;
}

// ---------------------------------------------------------------------------
// Pack dense region into x-pair float4s (5 MB read + 5 MB write, L2-hot).
// Entry i only *used* when its x-corner pair is valid, but reading t[i+1] is
// always in-bounds (i+1 <= DENSE_TOTAL < TOTAL_PARAMS).
// ---------------------------------------------------------------------------
__global__ void __launch_bounds__(256) dense_pack_kernel() {
    int i = blockIdx.x * blockDim.x + threadIdx.x;
    if (i >= DENSE_TOTAL) return;
    float2 a = g_table[i];
    float2 b = g_table[i + 1];
    g_dense4[i] = make_float4(a.x, a.y, b.x, b.y);
}

// ---------------------------------------------------------------------------
// Re-zero the accumulator for the next replay (runs concurrent with encode;
// touches only g_acc, which encode never reads).
// ---------------------------------------------------------------------------
__global__ void __launch_bounds__(256) zero_acc_kernel() {
    const size_t n = TOTAL_PARAMS;
    const size_t stride = (size_t)gridDim.x * blockDim.x;
    for (size_t i = (size_t)blockIdx.x * blockDim.x + threadIdx.x; i < n; i += stride)
        g_acc[i] = make_float4(0.f, 0.f, 0.f, 0.f);
}

// ---------------------------------------------------------------------------
// Encode: thread-per-point, 16 levels fully unrolled. Dense levels use 4
// aligned float4 pair-gathers; hash levels use 8 float2 gathers.
// ---------------------------------------------------------------------------
__global__ void __launch_bounds__(128) encode_kernel(
    const float* __restrict__ inp,
    const int*   __restrict__ bound_ptr,
    float*       __restrict__ out,
    int B) {
    int b = blockIdx.x * blockDim.x + threadIdx.x;
    if (b >= B) return;

    float bound = 1.0f;
    if (bound_ptr) {
        int raw = bound_ptr[0];
        bound = (raw > 0 && raw < 1000000) ? (float)raw : __int_as_float(raw);
    }
    const float half_inv = 0.5f / bound;

    float x0 = (inp[3 * b + 0] + bound) * half_inv;
    float x1 = (inp[3 * b + 1] + bound) * half_inv;
    float x2 = (inp[3 * b + 2] + bound) * half_inv;

    float r[32];

#pragma unroll
    for (int l = 0; l < 16; ++l) {
        const float scale = (float)((16 << l) - 1);
        float p0 = x0 * scale + 0.5f;      // align_corners=False offset
        float p1 = x1 * scale + 0.5f;
        float p2 = x2 * scale + 0.5f;
        float g0 = floorf(p0), g1 = floorf(p1), g2 = floorf(p2);
        float f0 = p0 - g0, f1 = p1 - g1, f2 = p2 - g2;
        int   i0 = (int)g0, i1 = (int)g1, i2 = (int)g2;

        const float wx0 = 1.0f - f0;
        const float wy0 = 1.0f - f1, wy1 = f1;
        const float wz0 = 1.0f - f2, wz1 = f2;
        float ax, ay;

        if (l < 3) {
            // Dense level: x-pair packed float4 gathers (4 loads).
            const int r1  = (l == 0) ? 17 : (l == 1) ? 33 : 65;
            const int off = (l == 0) ? 0  : (l == 1) ? 4920 : 40864;
            const int r1s = r1 * r1;
            int base = off + i0 + i1 * r1 + i2 * r1s;
            float4 d00 = __ldg(&g_dense4[base]);
            float4 d10 = __ldg(&g_dense4[base + r1]);
            float4 d01 = __ldg(&g_dense4[base + r1s]);
            float4 d11 = __ldg(&g_dense4[base + r1 + r1s]);
            float w00 = wy0 * wz0, w10 = wy1 * wz0;
            float w01 = wy0 * wz1, w11 = wy1 * wz1;
            // v = wx0*lo + f0*hi per corner-pair, weighted by wyz
            ax = w00 * fmaf(wx0, d00.x, f0 * d00.z)
               + w10 * fmaf(wx0, d10.x, f0 * d10.z)
               + w01 * fmaf(wx0, d01.x, f0 * d01.z)
               + w11 * fmaf(wx0, d11.x, f0 * d11.z);
            ay = w00 * fmaf(wx0, d00.y, f0 * d00.w)
               + w10 * fmaf(wx0, d10.y, f0 * d10.w)
               + w01 * fmaf(wx0, d01.y, f0 * d01.w)
               + w11 * fmaf(wx0, d11.y, f0 * d11.w);
        } else {
            // Hashed level: xor of per-dim prime products, mask 2^19-1.
            const int off = 315496 + (l - 3) * 524288;
            unsigned hx0 = (unsigned)i0;
            unsigned hx1 = hx0 + 1u;
            unsigned hy0 = (unsigned)i1 * PRIME_Y;
            unsigned hy1 = hy0 + PRIME_Y;
            unsigned hz0 = (unsigned)i2 * PRIME_Z;
            unsigned hz1 = hz0 + PRIME_Z;
            unsigned idx[8];
#pragma unroll
            for (int c = 0; c < 8; ++c) {
                unsigned h = ((c & 1) ? hx1 : hx0) ^
                             (((c >> 1) & 1) ? hy1 : hy0) ^
                             (((c >> 2) & 1) ? hz1 : hz0);
                idx[c] = h & HASH_MASK;
            }
            float2 v[8];
#pragma unroll
            for (int c = 0; c < 8; ++c)
                v[c] = __ldg(&g_table[off + (int)idx[c]]);
            ax = 0.0f; ay = 0.0f;
#pragma unroll
            for (int c = 0; c < 8; ++c) {
                float w = ((c & 1) ? f0 : wx0) *
                          (((c >> 1) & 1) ? wy1 : wy0) *
                          (((c >> 2) & 1) ? wz1 : wz0);
                ax = fmaf(w, v[c].x, ax);
                ay = fmaf(w, v[c].y, ay);
            }
        }
        r[2 * l]     = ax;
        r[2 * l + 1] = ay;
    }

    float4* o = (float4*)(out + (size_t)b * 32);
#pragma unroll
    for (int i = 0; i < 8; ++i)
        o[i] = make_float4(r[4 * i], r[4 * i + 1], r[4 * i + 2], r[4 * i + 3]);
}

// ---------------------------------------------------------------------------
// Launcher. Graph-capturable: kernel launches + event fork/join only.
// Dependency graph per call:
//   scatter -> finalize -> dense_pack -> encode        (main stream)
//                     \-> zero_acc (side stream)        (joined at end)
// zero_acc re-zeroes g_acc for the NEXT call; first call relies on static
// zero-initialization of __device__ globals. encode never touches g_acc, so
// the overlap is race-free. The final waitEvent ensures graph-replay N+1's
// scatter observes a zeroed accumulator.
// ---------------------------------------------------------------------------
extern "C" void kernel_launch(void* const* d_in, const int* in_sizes, int n_in,
                              void* d_out, int out_size) {
    const float*  inputs = (const float*) d_in[0];
    const float2* emb    = (const float2*)d_in[1];
    const float2* fs     = (const float2*)d_in[2];
    const int*    sidx   = (const int*)   d_in[3];
    const int*    bound  = (n_in >= 5) ? (const int*)d_in[4] : nullptr;

    int npts = in_sizes[3];          // 2,000,000
    int B    = in_sizes[0] / 3;      // 262,144

    scatter_kernel<<<(npts + 255) / 256, 256>>>(emb, sidx, npts);
    finalize_kernel<<<(TOTAL_PARAMS + 255) / 256, 256>>>(fs, TOTAL_PARAMS);

    // Fork: zero_acc depends only on finalize (last reader of g_acc).
    cudaStream_t side;
    cudaEvent_t ev_fork, ev_join;
    cudaStreamCreateWithFlags(&side, cudaStreamNonBlocking);
    cudaEventCreateWithFlags(&ev_fork, cudaEventDisableTiming);
    cudaEventCreateWithFlags(&ev_join, cudaEventDisableTiming);
    cudaEventRecord(ev_fork, 0);
    cudaStreamWaitEvent(side, ev_fork, 0);
    zero_acc_kernel<<<2048, 256, 0, side>>>();
    cudaEventRecord(ev_join, side);

    dense_pack_kernel<<<(DENSE_TOTAL + 255) / 256, 256>>>();
    encode_kernel<<<(B + 127) / 128, 128>>>(inputs, bound, (float*)d_out, B);

    // Join: next replay's scatter must see the zeroed accumulator.
    cudaStreamWaitEvent(0, ev_join, 0);
    // Note: stream/events intentionally not destroyed — kernel_launch is only
    // invoked a handful of times (correctness + capture), and destroying
    // capture-participating objects mid-capture is illegal.
}